// round 8
// baseline (speedup 1.0000x reference)
#include <cuda_runtime.h>
#include <cstdint>

#define Bsz 8
#define Nn 5000
#define NODES 8
#define THREADS 192          // 6 warps
// Q/K fp16 head-major strides (uint = f16x2 units)
#define NSTU 420
#define HSTU 52
// V f32 head-major strides (float units)
#define NSTF 802
#define HSTF 100

// smem layout in 4B units
#define U_W    0             // 5 * 64*32 = 10240 (all five weights, fp16 frag layout)
#define U_BIAS 10240         // 320 f32
#define U_A    10560         // 96*32 = 3072
#define U_Q    13632         // 3360
#define U_K    16992         // 3360
#define U_V    20352         // 6416 f32
#define U_TOT  26768         // 107,072 B -> 2 CTAs/SM

typedef unsigned long long u64;

// ---------------- helpers ----------------
__device__ __forceinline__ u64 fma2(u64 a, u64 b, u64 c) {
    u64 d; asm("fma.rn.f32x2 %0, %1, %2, %3;" : "=l"(d) : "l"(a), "l"(b), "l"(c)); return d;
}
__device__ __forceinline__ u64 mul2(u64 a, u64 b) {
    u64 d; asm("mul.rn.f32x2 %0, %1, %2;" : "=l"(d) : "l"(a), "l"(b)); return d;
}
__device__ __forceinline__ u64 dup2(float x) {
    u64 d; unsigned r = __float_as_uint(x);
    asm("mov.b64 %0, {%1, %1};" : "=l"(d) : "r"(r)); return d;
}
__device__ __forceinline__ float2 unpack2(u64 v) {
    unsigned lo, hi;
    asm("mov.b64 {%0, %1}, %2;" : "=r"(lo), "=r"(hi) : "l"(v));
    return make_float2(__uint_as_float(lo), __uint_as_float(hi));
}
__device__ __forceinline__ unsigned ph2(float x, float y) {
    unsigned r;
    asm("cvt.rn.f16x2.f32 %0, %1, %2;" : "=r"(r) : "f"(y), "f"(x));
    return r;
}
__device__ __forceinline__ u64 h2f2(unsigned h) {
    u64 r;
    asm("{ .reg .b16 l, h; .reg .f32 f0, f1;\n\t"
        "mov.b32 {l, h}, %1;\n\t"
        "cvt.f32.f16 f0, l;\n\tcvt.f32.f16 f1, h;\n\t"
        "mov.b64 %0, {f0, f1}; }" : "=l"(r) : "r"(h));
    return r;
}
__device__ __forceinline__ float h2_lo(unsigned h) {
    float f;
    asm("{ .reg .b16 l, hh; mov.b32 {l, hh}, %1; cvt.f32.f16 %0, l; }" : "=f"(f) : "r"(h));
    return f;
}
__device__ __forceinline__ float h2_hi(unsigned h) {
    float f;
    asm("{ .reg .b16 l, hh; mov.b32 {l, hh}, %1; cvt.f32.f16 %0, hh; }" : "=f"(f) : "r"(h));
    return f;
}
__device__ __forceinline__ void mma_f16(float d[4], const unsigned a[4],
                                        unsigned b0, unsigned b1) {
    asm volatile(
        "mma.sync.aligned.m16n8k16.row.col.f32.f16.f16.f32 "
        "{%0,%1,%2,%3}, {%4,%5,%6,%7}, {%8,%9}, {%0,%1,%2,%3};"
        : "+f"(d[0]), "+f"(d[1]), "+f"(d[2]), "+f"(d[3])
        : "r"(a[0]), "r"(a[1]), "r"(a[2]), "r"(a[3]), "r"(b0), "r"(b1));
}
__device__ __forceinline__ void ld_pair(const unsigned* p, unsigned& lo, unsigned& hi) {
    const u64 v = *(const u64*)p;
    lo = (unsigned)v; hi = (unsigned)(v >> 32);
}
__device__ __forceinline__ int posj(int jj) { return ((jj & 3) << 1) | (jj >> 2); }

// ---------------- kernel ----------------
__global__ void __launch_bounds__(THREADS, 2)
fused_h16_kernel(const float* __restrict__ X,
                 const float* __restrict__ STE_P,
                 const float* __restrict__ STE_Q,
                 const float* __restrict__ W21, const float* __restrict__ b21,
                 const float* __restrict__ W22, const float* __restrict__ b22,
                 const float* __restrict__ W23, const float* __restrict__ b23,
                 const float* __restrict__ W24, const float* __restrict__ b24,
                 const float* __restrict__ W25, const float* __restrict__ b25,
                 float* __restrict__ Out)
{
    extern __shared__ unsigned sm[];
    unsigned* sW = sm + U_W;
    float*    sBias = (float*)(sm + U_BIAS);
    unsigned* sA = sm + U_A;
    unsigned* sQ = sm + U_Q;
    unsigned* sK = sm + U_K;
    float*    sV = (float*)(sm + U_V);

    const int tid  = threadIdx.x;
    const int w    = tid >> 5;
    const int lane = tid & 31;
    const int gid  = lane >> 2;
    const int tig  = lane & 3;
    const int g3   = gid & 3;
    const int b    = blockIdx.y;
    const int n0   = blockIdx.x * NODES;
    const int row0 = w * 16;

    const int rp0 = row0 + gid, rp1 = rp0 + 8;
    const int nd0 = rp0 / 12, p0 = rp0 - nd0 * 12;
    const int nd1 = rp1 / 12, p1 = rp1 - nd1 * 12;

    const int srow = lane >> 4;
    const int sc4  = lane & 15;
    const int sp0  = posj((2 * sc4) & 7);
    int goff[8]; int sapos[8];
#pragma unroll
    for (int i = 0; i < 8; i++) {
        const int rp = row0 + 2 * i + srow;
        const int n = rp / 12, t = rp - n * 12;
        goff[i]  = ((b * 12 + t) * Nn + n0 + n) * 64 + sc4 * 4;
        sapos[i] = rp * 32 + (((sc4 >> 2) ^ (rp & 3)) << 3) + sp0;
    }

#define STAGE_W(Wg, ph)                                                     \
    {                                                                       \
        unsigned* dw = sW + (ph) * 2048;                                    \
        _Pragma("unroll")                                                   \
        for (int it = 0; it < 6; it++) {                                    \
            const int idx = tid + it * THREADS;                             \
            if (idx < 1024) {                                               \
                const int n = idx >> 4, c4 = idx & 15;                      \
                const float4 v = *(const float4*)((Wg) + n * 64 + c4 * 4);  \
                const int a0 = n * 32 + (((c4 >> 2) ^ (n & 3)) << 3)        \
                               + posj((2 * c4) & 7);                        \
                dw[a0]     = ph2(v.x, v.y);                                 \
                dw[a0 + 2] = ph2(v.z, v.w);                                 \
            }                                                               \
        }                                                                   \
    }

#define STS_IN(pf)                                                          \
    {                                                                       \
        _Pragma("unroll")                                                   \
        for (int i = 0; i < 8; i++) {                                       \
            sA[sapos[i]]     = ph2((pf)[i].x, (pf)[i].y);                   \
            sA[sapos[i] + 2] = ph2((pf)[i].z, (pf)[i].w);                   \
        }                                                                   \
    }

#define PREFETCH(src, pf)                                                   \
    {                                                                       \
        _Pragma("unroll")                                                   \
        for (int i = 0; i < 8; i++) (pf)[i] = *(const float4*)((src) + goff[i]); \
    }

#define LOAD_FRAGS(a)                                                       \
    {                                                                       \
        _Pragma("unroll")                                                   \
        for (int kc = 0; kc < 4; kc++) {                                    \
            const int off = ((kc ^ g3) << 3) + 2 * tig;                     \
            ld_pair(sA + rp0 * 32 + off, (a)[kc][0], (a)[kc][2]);           \
            ld_pair(sA + rp1 * 32 + off, (a)[kc][1], (a)[kc][3]);           \
        }                                                                   \
    }

#define MMA_ALL(d, a, ph)                                                   \
    {                                                                       \
        const unsigned* wb = sW + (ph) * 2048;                              \
        _Pragma("unroll")                                                   \
        for (int nt = 0; nt < 8; nt++) {                                    \
            (d)[nt][0] = 0.f; (d)[nt][1] = 0.f; (d)[nt][2] = 0.f; (d)[nt][3] = 0.f; \
            const unsigned* wr = wb + (nt * 8 + gid) * 32;                  \
            _Pragma("unroll")                                               \
            for (int kc = 0; kc < 4; kc++) {                                \
                unsigned b0, b1;                                            \
                ld_pair(wr + ((kc ^ g3) << 3) + 2 * tig, b0, b1);           \
                mma_f16((d)[nt], (a)[kc], b0, b1);                          \
            }                                                               \
        }                                                                   \
    }

#define EPI_QK(dst, boff)                                                   \
    {                                                                       \
        const float* bi = sBias + (boff);                                   \
        _Pragma("unroll")                                                   \
        for (int nt = 0; nt < 8; nt++) {                                    \
            const int c = nt * 8 + 2 * tig;                                 \
            (dst)[nd0 * NSTU + nt * HSTU + p0 * 4 + tig] =                  \
                ph2(fmaxf(d[nt][0] + bi[c], 0.f), fmaxf(d[nt][1] + bi[c + 1], 0.f)); \
            (dst)[nd1 * NSTU + nt * HSTU + p1 * 4 + tig] =                  \
                ph2(fmaxf(d[nt][2] + bi[c], 0.f), fmaxf(d[nt][3] + bi[c + 1], 0.f)); \
        }                                                                   \
    }

    unsigned a[4][4];
    float d[8][4];
    float4 pf[8];

    // ---- init: prefetch STE_Q, stage bias + ALL 5 weights, stage STE_Q ----
    PREFETCH(STE_Q, pf);
    if (tid < 64) {
        sBias[tid]       = b21[tid];
        sBias[64 + tid]  = b22[tid];
        sBias[128 + tid] = b23[tid];
        sBias[192 + tid] = b24[tid];
        sBias[256 + tid] = b25[tid];
    }
    STAGE_W(W21, 0);
    STAGE_W(W22, 1);
    STAGE_W(W23, 2);
    STAGE_W(W24, 3);
    STAGE_W(W25, 4);
    STS_IN(pf);
    __syncthreads();                                        // S1 (only weights/bias cross-warp)

    // ---- phase A: q -> sQ ----
    PREFETCH(STE_P, pf);
    LOAD_FRAGS(a);
    __syncwarp();
    MMA_ALL(d, a, 0);
    EPI_QK(sQ, 0);
    STS_IN(pf);                                             // STE_P over STE_Q (own rows)
    __syncwarp();

    // ---- phase B: k -> sK ----
    PREFETCH(X, pf);
    LOAD_FRAGS(a);
    __syncwarp();
    MMA_ALL(d, a, 1);
    EPI_QK(sK, 64);
    STS_IN(pf);                                             // X over STE_P (own rows)
    __syncwarp();

    // ---- phase C: v -> sV (f32 head-major) ----
    LOAD_FRAGS(a);
    MMA_ALL(d, a, 2);
    {
        const float* bi = sBias + 128;
#pragma unroll
        for (int nt = 0; nt < 8; nt++) {
            const int c = nt * 8 + 2 * tig;
            *(float2*)(sV + nd0 * NSTF + nt * HSTF + p0 * 8 + 2 * tig) =
                make_float2(fmaxf(d[nt][0] + bi[c], 0.f), fmaxf(d[nt][1] + bi[c + 1], 0.f));
            *(float2*)(sV + nd1 * NSTF + nt * HSTF + p1 * 8 + 2 * tig) =
                make_float2(fmaxf(d[nt][2] + bi[c], 0.f), fmaxf(d[nt][3] + bi[c + 1], 0.f));
        }
    }
    __syncthreads();                                        // S2: Q,K,V visible to all

    // ---- attention (f32 math; writes own sA rows in fp16 frag layout) ----
    {
        const int h  = lane & 7;
        const int pi = w * 4 + (lane >> 3);
        const int nd = pi / 3;
        const int q0 = (pi - nd * 3) * 4;
        const unsigned* Qb = sQ + nd * NSTU + h * HSTU + q0 * 4;
        const unsigned* Kb = sK + nd * NSTU + h * HSTU;
        const float*    Vb = sV + nd * NSTF + h * HSTF;
        const float scale = 0.35355339059327373f;

        u64 Qp[4][4];
#pragma unroll
        for (int jq = 0; jq < 4; jq++) {
            const uint4 qv = *(const uint4*)(Qb + jq * 4);
            Qp[jq][0] = h2f2(qv.x); Qp[jq][1] = h2f2(qv.y);
            Qp[jq][2] = h2f2(qv.z); Qp[jq][3] = h2f2(qv.w);
        }
        unsigned e2[4][6];
        float elo[4];
        float sum0 = 0.f, sum1 = 0.f, sum2 = 0.f, sum3 = 0.f;
#pragma unroll
        for (int p = 0; p < 12; p++) {
            const uint4 kv = *(const uint4*)(Kb + p * 4);
            const u64 k0 = h2f2(kv.x), k1 = h2f2(kv.y);
            const u64 k2 = h2f2(kv.z), k3 = h2f2(kv.w);
            float ee[4];
#pragma unroll
            for (int jq = 0; jq < 4; jq++) {
                u64 dd = fma2(Qp[jq][0], k0, fma2(Qp[jq][1], k1,
                         fma2(Qp[jq][2], k2, mul2(Qp[jq][3], k3))));
                const float2 t = unpack2(dd);
                ee[jq] = __expf(fmaf(t.x + t.y, scale, -8.0f));
            }
            sum0 += ee[0]; sum1 += ee[1]; sum2 += ee[2]; sum3 += ee[3];
            if (p & 1) {
#pragma unroll
                for (int jq = 0; jq < 4; jq++) e2[jq][p >> 1] = ph2(elo[jq], ee[jq]);
            } else {
#pragma unroll
                for (int jq = 0; jq < 4; jq++) elo[jq] = ee[jq];
            }
        }
        const float inv[4] = { __fdividef(1.f, sum0), __fdividef(1.f, sum1),
                               __fdividef(1.f, sum2), __fdividef(1.f, sum3) };

        u64 o[4][4];
        const u64 z = dup2(0.f);
#pragma unroll
        for (int jq = 0; jq < 4; jq++)
#pragma unroll
            for (int e = 0; e < 4; e++) o[jq][e] = z;
#pragma unroll
        for (int p = 0; p < 12; p++) {
            const float* vr = Vb + p * 8;
            const u64 v0 = *(const u64*)(vr + 0);
            const u64 v1 = *(const u64*)(vr + 2);
            const u64 v2 = *(const u64*)(vr + 4);
            const u64 v3 = *(const u64*)(vr + 6);
#pragma unroll
            for (int jq = 0; jq < 4; jq++) {
                const float ev = (p & 1) ? h2_hi(e2[jq][p >> 1]) : h2_lo(e2[jq][p >> 1]);
                const u64 aw = dup2(ev * inv[jq]);
                o[jq][0] = fma2(v0, aw, o[jq][0]);
                o[jq][1] = fma2(v1, aw, o[jq][1]);
                o[jq][2] = fma2(v2, aw, o[jq][2]);
                o[jq][3] = fma2(v3, aw, o[jq][3]);
            }
        }
        // write attn-out into own warp's sA rows (row = 16w + 4*(lane>>3) + jq)
#pragma unroll
        for (int jq = 0; jq < 4; jq++) {
            const int row = nd * 12 + q0 + jq;
            unsigned* base = sA + row * 32 + (((h >> 1) ^ (row & 3)) << 3);
#pragma unroll
            for (int e = 0; e < 4; e++) {
                const int jj = ((h & 1) << 2) + e;
                const float2 t = unpack2(o[jq][e]);
                base[posj(jj)] = ph2(t.x, t.y);
            }
        }
    }
    __syncwarp();                                           // attn STS -> phase D LDS (warp-local)

    // ---- phase D: h = relu(attn @ W24^T + b24) -> sA in place ----
    LOAD_FRAGS(a);
    __syncwarp();
    MMA_ALL(d, a, 3);
    {
        const float* bi = sBias + 192;
#pragma unroll
        for (int nt = 0; nt < 8; nt++) {
            const int c = nt * 8 + 2 * tig;
            const int colu = 4 * nt + tig;
            const int blk = colu >> 3, jj = colu & 7;
            sA[rp0 * 32 + ((blk ^ (rp0 & 3)) << 3) + posj(jj)] =
                ph2(fmaxf(d[nt][0] + bi[c], 0.f), fmaxf(d[nt][1] + bi[c + 1], 0.f));
            sA[rp1 * 32 + ((blk ^ (rp1 & 3)) << 3) + posj(jj)] =
                ph2(fmaxf(d[nt][2] + bi[c], 0.f), fmaxf(d[nt][3] + bi[c + 1], 0.f));
        }
    }
    __syncwarp();

    // ---- phase E: out = h @ W25^T + b25 -> global ----
    LOAD_FRAGS(a);
    MMA_ALL(d, a, 4);
    {
        float* o0 = Out + ((size_t)(b * 12 + p0) * Nn + (n0 + nd0)) * 64;
        float* o1 = Out + ((size_t)(b * 12 + p1) * Nn + (n0 + nd1)) * 64;
        const float* bi = sBias + 256;
#pragma unroll
        for (int nt = 0; nt < 8; nt++) {
            const int c = nt * 8 + tig * 2;
            *(float2*)(o0 + c) = make_float2(d[nt][0] + bi[c], d[nt][1] + bi[c + 1]);
            *(float2*)(o1 + c) = make_float2(d[nt][2] + bi[c], d[nt][3] + bi[c + 1]);
        }
    }
#undef STAGE_W
#undef STS_IN
#undef PREFETCH
#undef LOAD_FRAGS
#undef MMA_ALL
#undef EPI_QK
}

extern "C" void kernel_launch(void* const* d_in, const int* in_sizes, int n_in,
                              void* d_out, int out_size)
{
    const float* X     = (const float*)d_in[0];
    const float* STE_P = (const float*)d_in[1];
    const float* STE_Q = (const float*)d_in[2];
    const float* W21   = (const float*)d_in[3];
    const float* b21   = (const float*)d_in[4];
    const float* W22   = (const float*)d_in[5];
    const float* b22   = (const float*)d_in[6];
    const float* W23   = (const float*)d_in[7];
    const float* b23   = (const float*)d_in[8];
    const float* W24   = (const float*)d_in[9];
    const float* b24   = (const float*)d_in[10];
    const float* W25   = (const float*)d_in[11];
    const float* b25   = (const float*)d_in[12];
    float* Out = (float*)d_out;

    const size_t smem_bytes = (size_t)U_TOT * 4;            // 107,072 B -> 2 CTAs/SM

    cudaFuncSetAttribute(fused_h16_kernel,
                         cudaFuncAttributeMaxDynamicSharedMemorySize,
                         (int)smem_bytes);

    dim3 grid(Nn / NODES, Bsz);   // (625, 8)
    fused_h16_kernel<<<grid, THREADS, smem_bytes>>>(
        X, STE_P, STE_Q,
        W21, b21, W22, b22, W23, b23, W24, b24, W25, b25,
        Out);
}

// round 9
// speedup vs baseline: 1.0086x; 1.0086x over previous
#include <cuda_runtime.h>
#include <cstdint>

#define Bsz 8
#define Nn 5000
#define NODES 8
#define THREADS 192          // 6 warps
// fp16 head-major strides (uint = f16x2 units) for Q/K/V
#define NSTU 420
#define HSTU 52

// smem layout in 4B units
#define U_W    0             // 2 x 2048 (ping-pong weight, fp16 frag layout)
#define U_BIAS 4096          // 320 f32
#define U_A    4416          // 96*32 = 3072
#define U_Q    7488          // 3360
#define U_K    10848         // 3360
#define U_V    14208         // 3360
#define U_TOT  17568         // 70,272 B -> 3 CTAs/SM

typedef unsigned long long u64;

// ---------------- helpers ----------------
__device__ __forceinline__ u64 fma2(u64 a, u64 b, u64 c) {
    u64 d; asm("fma.rn.f32x2 %0, %1, %2, %3;" : "=l"(d) : "l"(a), "l"(b), "l"(c)); return d;
}
__device__ __forceinline__ u64 mul2(u64 a, u64 b) {
    u64 d; asm("mul.rn.f32x2 %0, %1, %2;" : "=l"(d) : "l"(a), "l"(b)); return d;
}
__device__ __forceinline__ u64 dup2(float x) {
    u64 d; unsigned r = __float_as_uint(x);
    asm("mov.b64 %0, {%1, %1};" : "=l"(d) : "r"(r)); return d;
}
__device__ __forceinline__ float2 unpack2(u64 v) {
    unsigned lo, hi;
    asm("mov.b64 {%0, %1}, %2;" : "=r"(lo), "=r"(hi) : "l"(v));
    return make_float2(__uint_as_float(lo), __uint_as_float(hi));
}
__device__ __forceinline__ unsigned ph2(float x, float y) {
    unsigned r;
    asm("cvt.rn.f16x2.f32 %0, %1, %2;" : "=r"(r) : "f"(y), "f"(x));
    return r;
}
__device__ __forceinline__ u64 h2f2(unsigned h) {
    u64 r;
    asm("{ .reg .b16 l, h; .reg .f32 f0, f1;\n\t"
        "mov.b32 {l, h}, %1;\n\t"
        "cvt.f32.f16 f0, l;\n\tcvt.f32.f16 f1, h;\n\t"
        "mov.b64 %0, {f0, f1}; }" : "=l"(r) : "r"(h));
    return r;
}
__device__ __forceinline__ float h2_lo(unsigned h) {
    float f;
    asm("{ .reg .b16 l, hh; mov.b32 {l, hh}, %1; cvt.f32.f16 %0, l; }" : "=f"(f) : "r"(h));
    return f;
}
__device__ __forceinline__ float h2_hi(unsigned h) {
    float f;
    asm("{ .reg .b16 l, hh; mov.b32 {l, hh}, %1; cvt.f32.f16 %0, hh; }" : "=f"(f) : "r"(h));
    return f;
}
__device__ __forceinline__ void mma_f16(float d[4], const unsigned a[4],
                                        unsigned b0, unsigned b1) {
    asm volatile(
        "mma.sync.aligned.m16n8k16.row.col.f32.f16.f16.f32 "
        "{%0,%1,%2,%3}, {%4,%5,%6,%7}, {%8,%9}, {%0,%1,%2,%3};"
        : "+f"(d[0]), "+f"(d[1]), "+f"(d[2]), "+f"(d[3])
        : "r"(a[0]), "r"(a[1]), "r"(a[2]), "r"(a[3]), "r"(b0), "r"(b1));
}
__device__ __forceinline__ void ld_pair(const unsigned* p, unsigned& lo, unsigned& hi) {
    const u64 v = *(const u64*)p;
    lo = (unsigned)v; hi = (unsigned)(v >> 32);
}
__device__ __forceinline__ int posj(int jj) { return ((jj & 3) << 1) | (jj >> 2); }

// ---------------- kernel ----------------
__global__ void __launch_bounds__(THREADS, 3)
fused_h16_kernel(const float* __restrict__ X,
                 const float* __restrict__ STE_P,
                 const float* __restrict__ STE_Q,
                 const float* __restrict__ W21, const float* __restrict__ b21,
                 const float* __restrict__ W22, const float* __restrict__ b22,
                 const float* __restrict__ W23, const float* __restrict__ b23,
                 const float* __restrict__ W24, const float* __restrict__ b24,
                 const float* __restrict__ W25, const float* __restrict__ b25,
                 float* __restrict__ Out)
{
    extern __shared__ unsigned sm[];
    unsigned* sW = sm + U_W;
    float*    sBias = (float*)(sm + U_BIAS);
    unsigned* sA = sm + U_A;
    unsigned* sQ = sm + U_Q;
    unsigned* sK = sm + U_K;
    unsigned* sV = sm + U_V;

    const int tid  = threadIdx.x;
    const int w    = tid >> 5;
    const int lane = tid & 31;
    const int gid  = lane >> 2;
    const int tig  = lane & 3;
    const int g3   = gid & 3;
    const int b    = blockIdx.y;
    const int n0   = blockIdx.x * NODES;
    const int row0 = w * 16;

    const int rp0 = row0 + gid, rp1 = rp0 + 8;
    const int nd0 = rp0 / 12, p0 = rp0 - nd0 * 12;
    const int nd1 = rp1 / 12, p1 = rp1 - nd1 * 12;

    const int srow = lane >> 4;
    const int sc4  = lane & 15;
    const int sp0  = posj((2 * sc4) & 7);
    int goff[8]; int sapos[8];
#pragma unroll
    for (int i = 0; i < 8; i++) {
        const int rp = row0 + 2 * i + srow;
        const int n = rp / 12, t = rp - n * 12;
        goff[i]  = ((b * 12 + t) * Nn + n0 + n) * 64 + sc4 * 4;
        sapos[i] = rp * 32 + (((sc4 >> 2) ^ (rp & 3)) << 3) + sp0;
    }

#define STAGE_W(Wg, buf)                                                    \
    {                                                                       \
        unsigned* dw = sW + (buf) * 2048;                                   \
        _Pragma("unroll")                                                   \
        for (int it = 0; it < 6; it++) {                                    \
            const int idx = tid + it * THREADS;                             \
            if (idx < 1024) {                                               \
                const int n = idx >> 4, c4 = idx & 15;                      \
                const float4 v = *(const float4*)((Wg) + n * 64 + c4 * 4);  \
                const int a0 = n * 32 + (((c4 >> 2) ^ (n & 3)) << 3)        \
                               + posj((2 * c4) & 7);                        \
                dw[a0]     = ph2(v.x, v.y);                                 \
                dw[a0 + 2] = ph2(v.z, v.w);                                 \
            }                                                               \
        }                                                                   \
    }

#define PREFETCH_H(src, hx)                                                 \
    {                                                                       \
        _Pragma("unroll")                                                   \
        for (int i = 0; i < 8; i++) {                                       \
            const float4 v = *(const float4*)((src) + goff[i]);             \
            (hx)[i].x = ph2(v.x, v.y);                                      \
            (hx)[i].y = ph2(v.z, v.w);                                      \
        }                                                                   \
    }

#define STS_IN(hx)                                                          \
    {                                                                       \
        _Pragma("unroll")                                                   \
        for (int i = 0; i < 8; i++) {                                       \
            sA[sapos[i]]     = (hx)[i].x;                                   \
            sA[sapos[i] + 2] = (hx)[i].y;                                   \
        }                                                                   \
    }

#define LOAD_FRAGS(a)                                                       \
    {                                                                       \
        _Pragma("unroll")                                                   \
        for (int kc = 0; kc < 4; kc++) {                                    \
            const int off = ((kc ^ g3) << 3) + 2 * tig;                     \
            ld_pair(sA + rp0 * 32 + off, (a)[kc][0], (a)[kc][2]);           \
            ld_pair(sA + rp1 * 32 + off, (a)[kc][1], (a)[kc][3]);           \
        }                                                                   \
    }

#define MMA_ALL(d, a, buf)                                                  \
    {                                                                       \
        const unsigned* wb = sW + (buf) * 2048;                             \
        _Pragma("unroll")                                                   \
        for (int nt = 0; nt < 8; nt++) {                                    \
            (d)[nt][0] = 0.f; (d)[nt][1] = 0.f; (d)[nt][2] = 0.f; (d)[nt][3] = 0.f; \
            const unsigned* wr = wb + (nt * 8 + gid) * 32;                  \
            _Pragma("unroll")                                               \
            for (int kc = 0; kc < 4; kc++) {                                \
                unsigned b0, b1;                                            \
                ld_pair(wr + ((kc ^ g3) << 3) + 2 * tig, b0, b1);           \
                mma_f16((d)[nt], (a)[kc], b0, b1);                          \
            }                                                               \
        }                                                                   \
    }

// epilogue -> fp16 head-major buffer (bias + relu)
#define EPI_HM(dst, boff)                                                   \
    {                                                                       \
        const float* bi = sBias + (boff);                                   \
        _Pragma("unroll")                                                   \
        for (int nt = 0; nt < 8; nt++) {                                    \
            const int c = nt * 8 + 2 * tig;                                 \
            (dst)[nd0 * NSTU + nt * HSTU + p0 * 4 + tig] =                  \
                ph2(fmaxf(d[nt][0] + bi[c], 0.f), fmaxf(d[nt][1] + bi[c + 1], 0.f)); \
            (dst)[nd1 * NSTU + nt * HSTU + p1 * 4 + tig] =                  \
                ph2(fmaxf(d[nt][2] + bi[c], 0.f), fmaxf(d[nt][3] + bi[c + 1], 0.f)); \
        }                                                                   \
    }

    unsigned a[4][4];
    float d[8][4];
    uint2 hx[8];

    // ---- init: bias + W21(buf0) + STE_Q staged ----
    PREFETCH_H(STE_Q, hx);
    if (tid < 64) {
        sBias[tid]       = b21[tid];
        sBias[64 + tid]  = b22[tid];
        sBias[128 + tid] = b23[tid];
        sBias[192 + tid] = b24[tid];
        sBias[256 + tid] = b25[tid];
    }
    STAGE_W(W21, 0);
    STS_IN(hx);
    __syncthreads();                                        // S1: W21 + inputs

    // ---- phase A: q -> sQ ; stage W22(buf1), STE_P -> sA ----
    PREFETCH_H(STE_P, hx);
    LOAD_FRAGS(a);
    __syncwarp();
    STS_IN(hx);
    STAGE_W(W22, 1);
    MMA_ALL(d, a, 0);
    EPI_HM(sQ, 0);
    __syncthreads();                                        // S2: W22 visible

    // ---- phase B: k -> sK ; stage W23(buf0), X -> sA ----
    PREFETCH_H(X, hx);
    LOAD_FRAGS(a);
    __syncwarp();
    STS_IN(hx);
    STAGE_W(W23, 0);
    MMA_ALL(d, a, 1);
    EPI_HM(sK, 64);
    __syncthreads();                                        // S3: W23 visible

    // ---- phase C: v -> sV (fp16) ; stage W24(buf1) ----
    LOAD_FRAGS(a);
    STAGE_W(W24, 1);
    MMA_ALL(d, a, 0);
    EPI_HM(sV, 128);
    __syncthreads();                                        // S4: Q,K,V + W24 visible

    // ---- attention (f32 math; fp16 Q/K/V) ; stage W25(buf0) ----
    {
        const int h  = lane & 7;
        const int pi = w * 4 + (lane >> 3);
        const int nd = pi / 3;
        const int q0 = (pi - nd * 3) * 4;
        const unsigned* Qb = sQ + nd * NSTU + h * HSTU + q0 * 4;
        const unsigned* Kb = sK + nd * NSTU + h * HSTU;
        const unsigned* Vb = sV + nd * NSTU + h * HSTU;
        const float scale = 0.35355339059327373f;

        u64 Qp[4][4];
#pragma unroll
        for (int jq = 0; jq < 4; jq++) {
            const uint4 qv = *(const uint4*)(Qb + jq * 4);
            Qp[jq][0] = h2f2(qv.x); Qp[jq][1] = h2f2(qv.y);
            Qp[jq][2] = h2f2(qv.z); Qp[jq][3] = h2f2(qv.w);
        }
        unsigned e2[4][6];
        float elo[4];
        float sum0 = 0.f, sum1 = 0.f, sum2 = 0.f, sum3 = 0.f;
#pragma unroll
        for (int p = 0; p < 12; p++) {
            const uint4 kv = *(const uint4*)(Kb + p * 4);
            const u64 k0 = h2f2(kv.x), k1 = h2f2(kv.y);
            const u64 k2 = h2f2(kv.z), k3 = h2f2(kv.w);
            float ee[4];
#pragma unroll
            for (int jq = 0; jq < 4; jq++) {
                u64 dd = fma2(Qp[jq][0], k0, fma2(Qp[jq][1], k1,
                         fma2(Qp[jq][2], k2, mul2(Qp[jq][3], k3))));
                const float2 t = unpack2(dd);
                ee[jq] = __expf(fmaf(t.x + t.y, scale, -8.0f));
            }
            sum0 += ee[0]; sum1 += ee[1]; sum2 += ee[2]; sum3 += ee[3];
            if (p & 1) {
#pragma unroll
                for (int jq = 0; jq < 4; jq++) e2[jq][p >> 1] = ph2(elo[jq], ee[jq]);
            } else {
#pragma unroll
                for (int jq = 0; jq < 4; jq++) elo[jq] = ee[jq];
            }
        }
        const float inv[4] = { __fdividef(1.f, sum0), __fdividef(1.f, sum1),
                               __fdividef(1.f, sum2), __fdividef(1.f, sum3) };

        u64 o[4][4];
        const u64 z = dup2(0.f);
#pragma unroll
        for (int jq = 0; jq < 4; jq++)
#pragma unroll
            for (int e = 0; e < 4; e++) o[jq][e] = z;
#pragma unroll
        for (int p = 0; p < 12; p++) {
            const uint4 vv = *(const uint4*)(Vb + p * 4);
            const u64 v0 = h2f2(vv.x), v1 = h2f2(vv.y);
            const u64 v2 = h2f2(vv.z), v3 = h2f2(vv.w);
#pragma unroll
            for (int jq = 0; jq < 4; jq++) {
                const float ev = (p & 1) ? h2_hi(e2[jq][p >> 1]) : h2_lo(e2[jq][p >> 1]);
                const u64 aw = dup2(ev * inv[jq]);
                o[jq][0] = fma2(v0, aw, o[jq][0]);
                o[jq][1] = fma2(v1, aw, o[jq][1]);
                o[jq][2] = fma2(v2, aw, o[jq][2]);
                o[jq][3] = fma2(v3, aw, o[jq][3]);
            }
        }
        STAGE_W(W25, 0);
        // write attn-out into own warp's sA rows (fp16 frag layout)
#pragma unroll
        for (int jq = 0; jq < 4; jq++) {
            const int row = nd * 12 + q0 + jq;
            unsigned* base = sA + row * 32 + (((h >> 1) ^ (row & 3)) << 3);
#pragma unroll
            for (int e = 0; e < 4; e++) {
                const int jj = ((h & 1) << 2) + e;
                const float2 t = unpack2(o[jq][e]);
                base[posj(jj)] = ph2(t.x, t.y);
            }
        }
    }
    __syncwarp();                                           // attn STS -> phase D LDS

    // ---- phase D: h = relu(attn @ W24^T + b24) -> sA in place ----
    LOAD_FRAGS(a);
    __syncwarp();
    MMA_ALL(d, a, 1);
    {
        const float* bi = sBias + 192;
#pragma unroll
        for (int nt = 0; nt < 8; nt++) {
            const int c = nt * 8 + 2 * tig;
            const int colu = 4 * nt + tig;
            const int blk = colu >> 3, jj = colu & 7;
            sA[rp0 * 32 + ((blk ^ (rp0 & 3)) << 3) + posj(jj)] =
                ph2(fmaxf(d[nt][0] + bi[c], 0.f), fmaxf(d[nt][1] + bi[c + 1], 0.f));
            sA[rp1 * 32 + ((blk ^ (rp1 & 3)) << 3) + posj(jj)] =
                ph2(fmaxf(d[nt][2] + bi[c], 0.f), fmaxf(d[nt][3] + bi[c + 1], 0.f));
        }
    }
    __syncthreads();                                        // S5: W25 visible

    // ---- phase E: out = h @ W25^T + b25 -> global ----
    LOAD_FRAGS(a);
    MMA_ALL(d, a, 0);
    {
        float* o0 = Out + ((size_t)(b * 12 + p0) * Nn + (n0 + nd0)) * 64;
        float* o1 = Out + ((size_t)(b * 12 + p1) * Nn + (n0 + nd1)) * 64;
        const float* bi = sBias + 256;
#pragma unroll
        for (int nt = 0; nt < 8; nt++) {
            const int c = nt * 8 + tig * 2;
            *(float2*)(o0 + c) = make_float2(d[nt][0] + bi[c], d[nt][1] + bi[c + 1]);
            *(float2*)(o1 + c) = make_float2(d[nt][2] + bi[c], d[nt][3] + bi[c + 1]);
        }
    }
#undef STAGE_W
#undef PREFETCH_H
#undef STS_IN
#undef LOAD_FRAGS
#undef MMA_ALL
#undef EPI_HM
}

extern "C" void kernel_launch(void* const* d_in, const int* in_sizes, int n_in,
                              void* d_out, int out_size)
{
    const float* X     = (const float*)d_in[0];
    const float* STE_P = (const float*)d_in[1];
    const float* STE_Q = (const float*)d_in[2];
    const float* W21   = (const float*)d_in[3];
    const float* b21   = (const float*)d_in[4];
    const float* W22   = (const float*)d_in[5];
    const float* b22   = (const float*)d_in[6];
    const float* W23   = (const float*)d_in[7];
    const float* b23   = (const float*)d_in[8];
    const float* W24   = (const float*)d_in[9];
    const float* b24   = (const float*)d_in[10];
    const float* W25   = (const float*)d_in[11];
    const float* b25   = (const float*)d_in[12];
    float* Out = (float*)d_out;

    const size_t smem_bytes = (size_t)U_TOT * 4;            // 70,272 B -> 3 CTAs/SM

    cudaFuncSetAttribute(fused_h16_kernel,
                         cudaFuncAttributeMaxDynamicSharedMemorySize,
                         (int)smem_bytes);

    dim3 grid(Nn / NODES, Bsz);   // (625, 8)
    fused_h16_kernel<<<grid, THREADS, smem_bytes>>>(
        X, STE_P, STE_Q,
        W21, b21, W22, b22, W23, b23, W24, b24, W25, b25,
        Out);
}

// round 10
// speedup vs baseline: 1.1873x; 1.1772x over previous
#include <cuda_runtime.h>
#include <cstdint>

#define Bsz 8
#define Nn 5000
#define NODES 6
#define THREADS 192          // 6 warps, one node per warp

// smem layout in 4B units
#define U_W    0             // 5 * 2048 (all five weights, fp16 frag layout)
#define U_BIAS 10240         // 320 f32
#define U_A    10560         // 96*32 fp16 frag slab (input staging only)
#define U_TOT  13632         // 54,528 B -> 3 CTAs/SM

typedef unsigned long long u64;

// ---------------- helpers ----------------
__device__ __forceinline__ unsigned ph2(float x, float y) {   // lo = x, hi = y
    unsigned r;
    asm("cvt.rn.f16x2.f32 %0, %1, %2;" : "=r"(r) : "f"(y), "f"(x));
    return r;
}
__device__ __forceinline__ void ld_pair(const unsigned* p, unsigned& lo, unsigned& hi) {
    const u64 v = *(const u64*)p;
    lo = (unsigned)v; hi = (unsigned)(v >> 32);
}
__device__ __forceinline__ int posj(int jj) { return ((jj & 3) << 1) | (jj >> 2); }

__device__ __forceinline__ void mma16(float d[4], const unsigned a[4],
                                      unsigned b0, unsigned b1) {
    asm volatile(
        "mma.sync.aligned.m16n8k16.row.col.f32.f16.f16.f32 "
        "{%0,%1,%2,%3}, {%4,%5,%6,%7}, {%8,%9}, {%0,%1,%2,%3};"
        : "+f"(d[0]), "+f"(d[1]), "+f"(d[2]), "+f"(d[3])
        : "r"(a[0]), "r"(a[1]), "r"(a[2]), "r"(a[3]), "r"(b0), "r"(b1));
}
__device__ __forceinline__ void mma8(float d[4], unsigned a0, unsigned a1, unsigned b0) {
    asm volatile(
        "mma.sync.aligned.m16n8k8.row.col.f32.f16.f16.f32 "
        "{%0,%1,%2,%3}, {%4,%5}, {%6}, {%0,%1,%2,%3};"
        : "+f"(d[0]), "+f"(d[1]), "+f"(d[2]), "+f"(d[3])
        : "r"(a0), "r"(a1), "r"(b0));
}

// ---------------- kernel ----------------
__global__ void __launch_bounds__(THREADS, 3)
fused_reg_kernel(const float* __restrict__ X,
                 const float* __restrict__ STE_P,
                 const float* __restrict__ STE_Q,
                 const float* __restrict__ W21, const float* __restrict__ b21,
                 const float* __restrict__ W22, const float* __restrict__ b22,
                 const float* __restrict__ W23, const float* __restrict__ b23,
                 const float* __restrict__ W24, const float* __restrict__ b24,
                 const float* __restrict__ W25, const float* __restrict__ b25,
                 float* __restrict__ Out)
{
    extern __shared__ unsigned sm[];
    unsigned* sW = sm + U_W;
    float*    sBias = (float*)(sm + U_BIAS);
    unsigned* sA = sm + U_A;

    const int tid  = threadIdx.x;
    const int w    = tid >> 5;
    const int lane = tid & 31;
    const int gid  = lane >> 2;
    const int tig  = lane & 3;
    const int g3   = gid & 3;
    const int b    = blockIdx.y;
    const int n0   = blockIdx.x * NODES;
    const int node = n0 + w;
    const bool valid = (node < Nn);

    const int r0 = 16 * w + gid;   // warp-slot row for q/p index gid
    const int r1 = r0 + 8;

    // staging indices: warp stages its node's 12 rows (6 iters of 2 rows)
    int gofs[6], sap[6];
#pragma unroll
    for (int i = 0; i < 6; i++) {
        const int idx = lane + 32 * i;
        const int row = idx >> 4, c4 = idx & 15;
        gofs[i] = ((b * 12 + row) * Nn + node) * 64 + c4 * 4;
        sap[i]  = (16 * w + row) * 32 + (((c4 >> 2) ^ (row & 3)) << 3)
                  + posj((2 * c4) & 7);
    }

    if (tid < 64) {
        sBias[tid]       = b21[tid];
        sBias[64 + tid]  = b22[tid];
        sBias[128 + tid] = b23[tid];
        sBias[192 + tid] = b24[tid];
        sBias[256 + tid] = b25[tid];
    }

    // stage all five weights (fp16 frag layout)
    {
        const float* Ws[5] = { W21, W22, W23, W24, W25 };
#pragma unroll
        for (int s = 0; s < 5; s++) {
            unsigned* dw = sW + s * 2048;
#pragma unroll
            for (int it = 0; it < 6; it++) {
                const int idx = tid + it * THREADS;
                if (idx < 1024) {
                    const int n = idx >> 4, c4 = idx & 15;
                    const float4 v = *(const float4*)(Ws[s] + n * 64 + c4 * 4);
                    const int a0 = n * 32 + (((c4 >> 2) ^ (n & 3)) << 3)
                                   + posj((2 * c4) & 7);
                    dw[a0]     = ph2(v.x, v.y);
                    dw[a0 + 2] = ph2(v.z, v.w);
                }
            }
        }
    }

    // zero pad rows 12-15 of this warp's slab
    ((uint4*)(sA + (16 * w + 12) * 32))[lane] = make_uint4(0, 0, 0, 0);

    uint2 hx[6];
    // stage STE_Q
    if (valid) {
#pragma unroll
        for (int i = 0; i < 6; i++) {
            const float4 v = *(const float4*)(STE_Q + gofs[i]);
            sA[sap[i]]     = ph2(v.x, v.y);
            sA[sap[i] + 2] = ph2(v.z, v.w);
        }
    }
    __syncthreads();                                     // the ONLY block sync

#define PREFETCH(src)                                                       \
    if (valid) {                                                            \
        _Pragma("unroll")                                                   \
        for (int i = 0; i < 6; i++) {                                       \
            const float4 v = *(const float4*)((src) + gofs[i]);             \
            hx[i].x = ph2(v.x, v.y);                                        \
            hx[i].y = ph2(v.z, v.w);                                        \
        }                                                                   \
    }

#define STS_IN()                                                            \
    if (valid) {                                                            \
        _Pragma("unroll")                                                   \
        for (int i = 0; i < 6; i++) {                                       \
            sA[sap[i]]     = hx[i].x;                                       \
            sA[sap[i] + 2] = hx[i].y;                                       \
        }                                                                   \
    }

#define LOAD_A(a)                                                           \
    {                                                                       \
        _Pragma("unroll")                                                   \
        for (int kc = 0; kc < 4; kc++) {                                    \
            const int off = ((kc ^ g3) << 3) + 2 * tig;                     \
            ld_pair(sA + r0 * 32 + off, (a)[kc][0], (a)[kc][2]);            \
            ld_pair(sA + r1 * 32 + off, (a)[kc][1], (a)[kc][3]);            \
        }                                                                   \
    }

// GEMM with A-frags in `a`, weights wsel, bias boff; pack bias+relu(*mult) to dst[8][2]
#define GEMM_PACK(wsel, boff, mult, dst)                                    \
    {                                                                       \
        _Pragma("unroll")                                                   \
        for (int nt = 0; nt < 8; nt++) {                                    \
            float dd[4] = {0.f, 0.f, 0.f, 0.f};                             \
            const unsigned* wr = sW + (wsel) * 2048 + (nt * 8 + gid) * 32;  \
            _Pragma("unroll")                                               \
            for (int kc = 0; kc < 4; kc++) {                                \
                unsigned b0, b1;                                            \
                ld_pair(wr + ((kc ^ g3) << 3) + 2 * tig, b0, b1);           \
                mma16(dd, a[kc], b0, b1);                                   \
            }                                                               \
            const float2 bc = *(const float2*)(sBias + (boff) + nt * 8 + 2 * tig); \
            (dst)[nt][0] = ph2(fmaxf(dd[0] + bc.x, 0.f) * (mult),           \
                               fmaxf(dd[1] + bc.y, 0.f) * (mult));          \
            (dst)[nt][1] = ph2(fmaxf(dd[2] + bc.x, 0.f) * (mult),           \
                               fmaxf(dd[3] + bc.y, 0.f) * (mult));          \
        }                                                                   \
    }

// GEMM with A-frags from packed reg-pairs src[8][2] (C-layout==A-layout identity)
#define GEMM_REG(wsel, src, nt, dd)                                         \
    {                                                                       \
        const unsigned* wr = sW + (wsel) * 2048 + ((nt) * 8 + gid) * 32;    \
        _Pragma("unroll")                                                   \
        for (int kc = 0; kc < 4; kc++) {                                    \
            unsigned aR[4] = { (src)[2 * kc][0], (src)[2 * kc][1],          \
                               (src)[2 * kc + 1][0], (src)[2 * kc + 1][1] };\
            unsigned b0, b1;                                                \
            ld_pair(wr + ((kc ^ g3) << 3) + 2 * tig, b0, b1);               \
            mma16(dd, aR, b0, b1);                                          \
        }                                                                   \
    }

    unsigned a[4][4];
    unsigned qa[8][2], kb[8][2], vb[8][2], oa[8][2], ha[8][2];
    const float scale = 0.35355339059327373f;            // 1/sqrt(8), folded into Q

    // ---- phase A: Q (scaled) -> qa regs ----
    PREFETCH(STE_P);
    LOAD_A(a);
    __syncwarp();
    STS_IN();
    GEMM_PACK(0, 0, scale, qa);
    __syncwarp();

    // ---- phase B: K -> kb regs ----
    PREFETCH(X);
    LOAD_A(a);
    __syncwarp();
    STS_IN();
    GEMM_PACK(1, 64, 1.f, kb);
    __syncwarp();

    // ---- phase C (transposed): Vt = W23 * X^T -> vb regs (O-MMA B-frags) ----
#pragma unroll
    for (int mt = 0; mt < 4; mt++) {
        unsigned wa[4][4];
#pragma unroll
        for (int kc = 0; kc < 4; kc++) {
            const int off = ((kc ^ g3) << 3) + 2 * tig;
            ld_pair(sW + 2 * 2048 + (16 * mt + gid) * 32 + off, wa[kc][0], wa[kc][2]);
            ld_pair(sW + 2 * 2048 + (16 * mt + 8 + gid) * 32 + off, wa[kc][1], wa[kc][3]);
        }
        const float bj0 = sBias[128 + 16 * mt + gid];
        const float bj1 = sBias[128 + 16 * mt + 8 + gid];
        float d0[4] = {0.f, 0.f, 0.f, 0.f};
        float d1[4] = {0.f, 0.f, 0.f, 0.f};
#pragma unroll
        for (int kc = 0; kc < 4; kc++) {
            const int off = ((kc ^ g3) << 3) + 2 * tig;
            unsigned b0, b1;
            ld_pair(sA + r0 * 32 + off, b0, b1);
            mma16(d0, wa[kc], b0, b1);
            ld_pair(sA + r1 * 32 + off, b0, b1);
            mma16(d1, wa[kc], b0, b1);
        }
        vb[2 * mt][0]     = ph2(fmaxf(d0[0] + bj0, 0.f), fmaxf(d0[1] + bj0, 0.f));
        vb[2 * mt][1]     = ph2(fmaxf(d1[0] + bj0, 0.f), fmaxf(d1[1] + bj0, 0.f));
        vb[2 * mt + 1][0] = ph2(fmaxf(d0[2] + bj1, 0.f), fmaxf(d0[3] + bj1, 0.f));
        vb[2 * mt + 1][1] = ph2(fmaxf(d1[2] + bj1, 0.f), fmaxf(d1[3] + bj1, 0.f));
    }

    // ---- attention: per head, all in registers ----
#pragma unroll
    for (int h = 0; h < 8; h++) {
        float s1[4] = {0.f, 0.f, 0.f, 0.f};
        float s2[4] = {0.f, 0.f, 0.f, 0.f};
        mma8(s1, qa[h][0], qa[h][1], kb[h][0]);          // p = 0..7
        mma8(s2, qa[h][0], qa[h][1], kb[h][1]);          // p = 8..15 (12-15 masked)
        const float e10 = __expf(s1[0] - 8.f), e11 = __expf(s1[1] - 8.f);
        const float e12 = __expf(s1[2] - 8.f), e13 = __expf(s1[3] - 8.f);
        float e20 = 0.f, e21 = 0.f, e22 = 0.f, e23 = 0.f;
        if (tig < 2) {                                   // p = 8+2tig < 12
            e20 = __expf(s2[0] - 8.f); e21 = __expf(s2[1] - 8.f);
            e22 = __expf(s2[2] - 8.f); e23 = __expf(s2[3] - 8.f);
        }
        float sumA = e10 + e11 + e20 + e21;
        float sumB = e12 + e13 + e22 + e23;
        sumA += __shfl_xor_sync(0xffffffffu, sumA, 1);
        sumA += __shfl_xor_sync(0xffffffffu, sumA, 2);
        sumB += __shfl_xor_sync(0xffffffffu, sumB, 1);
        sumB += __shfl_xor_sync(0xffffffffu, sumB, 2);
        const float invA = __fdividef(1.f, sumA);
        const float invB = __fdividef(1.f, sumB);
        unsigned pa[4];
        pa[0] = ph2(e10 * invA, e11 * invA);             // P[gid][2tig..]
        pa[1] = ph2(e12 * invB, e13 * invB);             // P[gid+8][2tig..]
        pa[2] = ph2(e20 * invA, e21 * invA);             // P[gid][8+2tig..]
        pa[3] = ph2(e22 * invB, e23 * invB);             // P[gid+8][8+2tig..]
        float ov[4] = {0.f, 0.f, 0.f, 0.f};
        mma16(ov, pa, vb[h][0], vb[h][1]);
        oa[h][0] = ph2(ov[0], ov[1]);
        oa[h][1] = ph2(ov[2], ov[3]);
    }

    // ---- phase D: H = relu(attn @ W24^T + b24) -> ha regs ----
#pragma unroll
    for (int nt = 0; nt < 8; nt++) {
        float dd[4] = {0.f, 0.f, 0.f, 0.f};
        GEMM_REG(3, oa, nt, dd);
        const float2 bc = *(const float2*)(sBias + 192 + nt * 8 + 2 * tig);
        ha[nt][0] = ph2(fmaxf(dd[0] + bc.x, 0.f), fmaxf(dd[1] + bc.y, 0.f));
        ha[nt][1] = ph2(fmaxf(dd[2] + bc.x, 0.f), fmaxf(dd[3] + bc.y, 0.f));
    }

    // ---- phase E: out = H @ W25^T + b25 -> global ----
    {
        float* o0 = Out + ((size_t)(b * 12 + gid) * Nn + node) * 64;
        float* o1 = Out + ((size_t)(b * 12 + gid + 8) * Nn + node) * 64;
#pragma unroll
        for (int nt = 0; nt < 8; nt++) {
            float dd[4] = {0.f, 0.f, 0.f, 0.f};
            GEMM_REG(4, ha, nt, dd);
            const float2 bc = *(const float2*)(sBias + 256 + nt * 8 + 2 * tig);
            if (valid) {
                *(float2*)(o0 + nt * 8 + 2 * tig) =
                    make_float2(dd[0] + bc.x, dd[1] + bc.y);
                if (gid < 4)
                    *(float2*)(o1 + nt * 8 + 2 * tig) =
                        make_float2(dd[2] + bc.x, dd[3] + bc.y);
            }
        }
    }
#undef PREFETCH
#undef STS_IN
#undef LOAD_A
#undef GEMM_PACK
#undef GEMM_REG
}

extern "C" void kernel_launch(void* const* d_in, const int* in_sizes, int n_in,
                              void* d_out, int out_size)
{
    const float* X     = (const float*)d_in[0];
    const float* STE_P = (const float*)d_in[1];
    const float* STE_Q = (const float*)d_in[2];
    const float* W21   = (const float*)d_in[3];
    const float* b21   = (const float*)d_in[4];
    const float* W22   = (const float*)d_in[5];
    const float* b22   = (const float*)d_in[6];
    const float* W23   = (const float*)d_in[7];
    const float* b23   = (const float*)d_in[8];
    const float* W24   = (const float*)d_in[9];
    const float* b24   = (const float*)d_in[10];
    const float* W25   = (const float*)d_in[11];
    const float* b25   = (const float*)d_in[12];
    float* Out = (float*)d_out;

    const size_t smem_bytes = (size_t)U_TOT * 4;          // 54,528 B -> 3 CTAs/SM

    cudaFuncSetAttribute(fused_reg_kernel,
                         cudaFuncAttributeMaxDynamicSharedMemorySize,
                         (int)smem_bytes);

    dim3 grid((Nn + NODES - 1) / NODES, Bsz);   // (834, 8)
    fused_reg_kernel<<<grid, THREADS, smem_bytes>>>(
        X, STE_P, STE_Q,
        W21, b21, W22, b22, W23, b23, W24, b24, W25, b25,
        Out);
}